// round 6
// baseline (speedup 1.0000x reference)
#include <cuda_runtime.h>
#include <cstdint>

// ReadingLayerReLU via mma.sync.m16n8k8 tf32 + ldmatrix, 64x64 warp tiles.
// key = relu(x @ W^T)        : M=16384, N=256,  K=256
// val[b] = key[b] @ mem[b]^T : M=2048,  N=1024, K=256, batch=8
// Both NT (K contiguous in both operands).

#define BM 128
#define BN 256
#define BK 16
#define LDSS 20   // smem row stride (words); r*20 mod 32 distinct over 8 rows -> LDSM conflict-free

#define AW (BM * LDSS)     // 2560 words per A tile
#define BW (BN * LDSS)     // 5120 words per B tile
#define SMEM_WORDS (2 * (AW + BW))   // 15360 words = 61440 B

__device__ __forceinline__ uint32_t f2tf32(float f) {
    uint32_t r;
    asm("cvt.rna.tf32.f32 %0, %1;" : "=r"(r) : "f"(f));
    return r;
}

__device__ __forceinline__ uint32_t s2u(const void* p) {
    uint32_t a;
    asm("{ .reg .u64 t; cvta.to.shared.u64 t, %1; cvt.u32.u64 %0, t; }" : "=r"(a) : "l"(p));
    return a;
}

__device__ __forceinline__ void ldsm4(uint32_t& r0, uint32_t& r1, uint32_t& r2, uint32_t& r3,
                                      uint32_t addr) {
    asm volatile("ldmatrix.sync.aligned.m8n8.x4.shared.b16 {%0,%1,%2,%3}, [%4];"
                 : "=r"(r0), "=r"(r1), "=r"(r2), "=r"(r3) : "r"(addr));
}

__device__ __forceinline__ uint4 cvt4(float4 v) {
    uint4 u;
    u.x = f2tf32(v.x); u.y = f2tf32(v.y); u.z = f2tf32(v.z); u.w = f2tf32(v.w);
    return u;
}

template<bool RELU>
__global__ __launch_bounds__(256)
void tf32_mma_nt(const float* __restrict__ A, const float* __restrict__ B,
                 float* __restrict__ C, int K, int N,
                 long sA, long sB, long sC)
{
    extern __shared__ uint32_t smem[];
    uint32_t* As[2] = { smem,            smem + AW };
    uint32_t* Bs[2] = { smem + 2 * AW,   smem + 2 * AW + BW };

    const int tid  = threadIdx.x;
    const int lane = tid & 31;
    const int warp = tid >> 5;
    const int wm   = warp >> 2;    // 0..1 -> M offset wm*64
    const int wn   = warp & 3;     // 0..3 -> N offset wn*64

    A += (long)blockIdx.z * sA + (long)blockIdx.y * BM * K;
    B += (long)blockIdx.z * sB + (long)blockIdx.x * BN * K;
    C += (long)blockIdx.z * sC;

    // Global loads: A 128x16 -> 2 float4/thread; B 256x16 -> 4 float4/thread.
    const int r0 = tid >> 2;          // 0..63
    const int c0 = (tid & 3) * 4;     // 0,4,8,12

    const uint32_t stsA0 = (uint32_t)(r0 * LDSS + c0);
    const uint32_t stsA1 = (uint32_t)((r0 + 64) * LDSS + c0);
    const uint32_t stsB0 = stsA0;
    const uint32_t stsB1 = stsA1;
    const uint32_t stsB2 = (uint32_t)((r0 + 128) * LDSS + c0);
    const uint32_t stsB3 = (uint32_t)((r0 + 192) * LDSS + c0);

    // LDSM lane address bases (byte offsets within a tile)
    const int la_rowA = wm * 64 + ((lane >> 3) & 1) * 8 + (lane & 7);
    const int la_colA = (lane >> 4) * 4;
    const uint32_t aBase = (uint32_t)(la_rowA * LDSS + la_colA) * 4u;
    const int la_rowB = wn * 64 + (lane >> 4) * 8 + (lane & 7);
    const int la_colB = ((lane >> 3) & 1) * 4;
    const uint32_t bBase = (uint32_t)(la_rowB * LDSS + la_colB) * 4u;

    const uint32_t sA0 = s2u(As[0]);
    const uint32_t sA1 = s2u(As[1]);
    const uint32_t sB0 = s2u(Bs[0]);
    const uint32_t sB1 = s2u(Bs[1]);

    float4 la0, la1, lb0, lb1, lb2, lb3;
    const int nchunks = K / BK;       // 16

    // prologue: chunk 0 -> buf 0
    la0 = *(const float4*)(A + (long)r0         * K + c0);
    la1 = *(const float4*)(A + (long)(r0 + 64)  * K + c0);
    lb0 = *(const float4*)(B + (long)r0         * K + c0);
    lb1 = *(const float4*)(B + (long)(r0 + 64)  * K + c0);
    lb2 = *(const float4*)(B + (long)(r0 + 128) * K + c0);
    lb3 = *(const float4*)(B + (long)(r0 + 192) * K + c0);
    *(uint4*)&As[0][stsA0] = cvt4(la0);
    *(uint4*)&As[0][stsA1] = cvt4(la1);
    *(uint4*)&Bs[0][stsB0] = cvt4(lb0);
    *(uint4*)&Bs[0][stsB1] = cvt4(lb1);
    *(uint4*)&Bs[0][stsB2] = cvt4(lb2);
    *(uint4*)&Bs[0][stsB3] = cvt4(lb3);
    __syncthreads();

    float acc[4][8][4];
    #pragma unroll
    for (int mi = 0; mi < 4; mi++)
        #pragma unroll
        for (int ni = 0; ni < 8; ni++)
            #pragma unroll
            for (int j = 0; j < 4; j++)
                acc[mi][ni][j] = 0.0f;

    #pragma unroll 1
    for (int kc = 0; kc < nchunks; kc++) {
        const int buf = kc & 1;
        const uint32_t aS = buf ? sA1 : sA0;
        const uint32_t bS = buf ? sB1 : sB0;

        // prefetch next chunk from global into registers
        if (kc + 1 < nchunks) {
            const float* Ap = A + (kc + 1) * BK;
            const float* Bp = B + (kc + 1) * BK;
            la0 = *(const float4*)(Ap + (long)r0         * K + c0);
            la1 = *(const float4*)(Ap + (long)(r0 + 64)  * K + c0);
            lb0 = *(const float4*)(Bp + (long)r0         * K + c0);
            lb1 = *(const float4*)(Bp + (long)(r0 + 64)  * K + c0);
            lb2 = *(const float4*)(Bp + (long)(r0 + 128) * K + c0);
            lb3 = *(const float4*)(Bp + (long)(r0 + 192) * K + c0);
        }

        #pragma unroll
        for (int ks = 0; ks < 2; ks++) {
            const uint32_t kByte = (uint32_t)(ks * 8) * 4u;
            uint32_t af[4][4], bf[8][2];
            #pragma unroll
            for (int mi = 0; mi < 4; mi++)
                ldsm4(af[mi][0], af[mi][1], af[mi][2], af[mi][3],
                      aS + aBase + (uint32_t)(mi * 16 * LDSS) * 4u + kByte);
            #pragma unroll
            for (int j = 0; j < 4; j++)
                ldsm4(bf[2 * j][0], bf[2 * j][1], bf[2 * j + 1][0], bf[2 * j + 1][1],
                      bS + bBase + (uint32_t)(j * 16 * LDSS) * 4u + kByte);

            #pragma unroll
            for (int mi = 0; mi < 4; mi++)
                #pragma unroll
                for (int ni = 0; ni < 8; ni++)
                    asm volatile(
                        "mma.sync.aligned.m16n8k8.row.col.f32.tf32.tf32.f32 "
                        "{%0,%1,%2,%3}, {%4,%5,%6,%7}, {%8,%9}, {%0,%1,%2,%3};"
                        : "+f"(acc[mi][ni][0]), "+f"(acc[mi][ni][1]),
                          "+f"(acc[mi][ni][2]), "+f"(acc[mi][ni][3])
                        : "r"(af[mi][0]), "r"(af[mi][1]), "r"(af[mi][2]), "r"(af[mi][3]),
                          "r"(bf[ni][0]), "r"(bf[ni][1]));
        }

        // store prefetched chunk to the other buffer
        if (kc + 1 < nchunks) {
            uint32_t* a = As[buf ^ 1];
            uint32_t* b = Bs[buf ^ 1];
            *(uint4*)&a[stsA0] = cvt4(la0);
            *(uint4*)&a[stsA1] = cvt4(la1);
            *(uint4*)&b[stsB0] = cvt4(lb0);
            *(uint4*)&b[stsB1] = cvt4(lb1);
            *(uint4*)&b[stsB2] = cvt4(lb2);
            *(uint4*)&b[stsB3] = cvt4(lb3);
        }
        __syncthreads();
    }

    // Epilogue: c0,c1 at (row, col), c2,c3 at (row+8, col); col pair = 2*(lane&3)
    #pragma unroll
    for (int mi = 0; mi < 4; mi++) {
        const long row = (long)blockIdx.y * BM + wm * 64 + mi * 16 + (lane >> 2);
        #pragma unroll
        for (int ni = 0; ni < 8; ni++) {
            const long col = (long)blockIdx.x * BN + wn * 64 + ni * 8 + (lane & 3) * 2;
            float2 v0 = make_float2(acc[mi][ni][0], acc[mi][ni][1]);
            float2 v1 = make_float2(acc[mi][ni][2], acc[mi][ni][3]);
            if (RELU) {
                v0.x = fmaxf(v0.x, 0.0f); v0.y = fmaxf(v0.y, 0.0f);
                v1.x = fmaxf(v1.x, 0.0f); v1.y = fmaxf(v1.y, 0.0f);
            }
            *(float2*)(C + row * N + col)       = v0;
            *(float2*)(C + (row + 8) * N + col) = v1;
        }
    }
}

extern "C" void kernel_launch(void* const* d_in, const int* in_sizes, int n_in,
                              void* d_out, int out_size)
{
    (void)in_sizes; (void)n_in; (void)out_size;

    const float* x   = (const float*)d_in[0];  // (8,2048,256)
    const float* mem = (const float*)d_in[1];  // (8,1024,256)
    const float* W   = (const float*)d_in[2];  // (256,256)

    float* key = (float*)d_out;                      // 16384*256
    float* val = (float*)d_out + (long)16384 * 256;  // 16384*1024

    const int smemB = SMEM_WORDS * 4;

    static int configured = 0;
    if (!configured) {
        cudaFuncSetAttribute(tf32_mma_nt<true>,
                             cudaFuncAttributeMaxDynamicSharedMemorySize, smemB);
        cudaFuncSetAttribute(tf32_mma_nt<false>,
                             cudaFuncAttributeMaxDynamicSharedMemorySize, smemB);
        configured = 1;
    }

    // GEMM 1: key = relu(x @ W^T)  M=16384 N=256 K=256  -> grid (1,128)
    {
        dim3 grid(256 / BN, 16384 / BM, 1);
        tf32_mma_nt<true><<<grid, 256, smemB>>>(x, W, key, 256, 256, 0, 0, 0);
    }
    // GEMM 2: val[b] = key[b] @ mem[b]^T  M=2048 N=1024 K=256, batch 8 -> grid (4,16,8)
    {
        dim3 grid(1024 / BN, 2048 / BM, 8);
        tf32_mma_nt<false><<<grid, 256, smemB>>>(
            key, mem, val, 256, 1024,
            (long)2048 * 256, (long)1024 * 256, (long)2048 * 1024);
    }
}

// round 8
// speedup vs baseline: 1.1963x; 1.1963x over previous
#include <cuda_runtime.h>
#include <cstdint>

// ReadingLayerReLU via mma.sync.m16n8k8 tf32 + ldmatrix.
// 128x128 block tile, 128 threads (4 warps, 2x2), 64x64 warp tile, double buffer.
// key = relu(x @ W^T)        : M=16384, N=256,  K=256
// val[b] = key[b] @ mem[b]^T : M=2048,  N=1024, K=256, batch=8

#define BM 128
#define BN 128
#define BK 16
#define LDSS 20   // smem row stride (words); r*20 mod 32 distinct over 8 rows -> LDSM conflict-free

#define AW (BM * LDSS)               // 2560 words per A tile
#define BW (BN * LDSS)               // 2560 words per B tile
#define SMEM_WORDS (2 * (AW + BW))   // 10240 words = 40960 B

__device__ __forceinline__ uint32_t f2tf32(float f) {
    uint32_t r;
    asm("cvt.rna.tf32.f32 %0, %1;" : "=r"(r) : "f"(f));
    return r;
}

__device__ __forceinline__ uint32_t s2u(const void* p) {
    uint32_t a;
    asm("{ .reg .u64 t; cvta.to.shared.u64 t, %1; cvt.u32.u64 %0, t; }" : "=r"(a) : "l"(p));
    return a;
}

__device__ __forceinline__ void ldsm4(uint32_t& r0, uint32_t& r1, uint32_t& r2, uint32_t& r3,
                                      uint32_t addr) {
    asm volatile("ldmatrix.sync.aligned.m8n8.x4.shared.b16 {%0,%1,%2,%3}, [%4];"
                 : "=r"(r0), "=r"(r1), "=r"(r2), "=r"(r3) : "r"(addr));
}

__device__ __forceinline__ uint4 cvt4(float4 v) {
    uint4 u;
    u.x = f2tf32(v.x); u.y = f2tf32(v.y); u.z = f2tf32(v.z); u.w = f2tf32(v.w);
    return u;
}

template<bool RELU>
__global__ __launch_bounds__(128, 2)
void tf32_mma_nt(const float* __restrict__ A, const float* __restrict__ B,
                 float* __restrict__ C, int K, int N,
                 long sA, long sB, long sC)
{
    extern __shared__ uint32_t smem[];
    uint32_t* As[2] = { smem,          smem + AW };
    uint32_t* Bs[2] = { smem + 2 * AW, smem + 2 * AW + BW };

    const int tid  = threadIdx.x;
    const int lane = tid & 31;
    const int warp = tid >> 5;     // 0..3
    const int wm   = warp >> 1;    // 0..1 -> M offset wm*64
    const int wn   = warp & 1;     // 0..1 -> N offset wn*64

    A += (long)blockIdx.z * sA + (long)blockIdx.y * BM * K;
    B += (long)blockIdx.z * sB + (long)blockIdx.x * BN * K;
    C += (long)blockIdx.z * sC;

    // Global loads: each matrix 128x16 floats = 512 float4; 128 threads -> 4 float4 each.
    const int r0 = tid >> 2;          // 0..31 (rows r0, +32, +64, +96)
    const int c0 = (tid & 3) * 4;     // 0,4,8,12

    const uint32_t sts0 = (uint32_t)(r0 * LDSS + c0);
    const uint32_t sts1 = (uint32_t)((r0 + 32) * LDSS + c0);
    const uint32_t sts2 = (uint32_t)((r0 + 64) * LDSS + c0);
    const uint32_t sts3 = (uint32_t)((r0 + 96) * LDSS + c0);

    // LDSM lane address bases (byte offsets within a tile)
    const int la_rowA = wm * 64 + ((lane >> 3) & 1) * 8 + (lane & 7);
    const int la_colA = (lane >> 4) * 4;
    const uint32_t aBase = (uint32_t)(la_rowA * LDSS + la_colA) * 4u;
    const int la_rowB = wn * 64 + (lane >> 4) * 8 + (lane & 7);
    const int la_colB = ((lane >> 3) & 1) * 4;
    const uint32_t bBase = (uint32_t)(la_rowB * LDSS + la_colB) * 4u;

    const uint32_t sA0 = s2u(As[0]);
    const uint32_t sA1 = s2u(As[1]);
    const uint32_t sB0 = s2u(Bs[0]);
    const uint32_t sB1 = s2u(Bs[1]);

    float4 la0, la1, la2, la3, lb0, lb1, lb2, lb3;
    const int nchunks = K / BK;       // 16

    // prologue: chunk 0 -> buf 0
    la0 = *(const float4*)(A + (long)r0        * K + c0);
    la1 = *(const float4*)(A + (long)(r0 + 32) * K + c0);
    la2 = *(const float4*)(A + (long)(r0 + 64) * K + c0);
    la3 = *(const float4*)(A + (long)(r0 + 96) * K + c0);
    lb0 = *(const float4*)(B + (long)r0        * K + c0);
    lb1 = *(const float4*)(B + (long)(r0 + 32) * K + c0);
    lb2 = *(const float4*)(B + (long)(r0 + 64) * K + c0);
    lb3 = *(const float4*)(B + (long)(r0 + 96) * K + c0);
    *(uint4*)&As[0][sts0] = cvt4(la0);
    *(uint4*)&As[0][sts1] = cvt4(la1);
    *(uint4*)&As[0][sts2] = cvt4(la2);
    *(uint4*)&As[0][sts3] = cvt4(la3);
    *(uint4*)&Bs[0][sts0] = cvt4(lb0);
    *(uint4*)&Bs[0][sts1] = cvt4(lb1);
    *(uint4*)&Bs[0][sts2] = cvt4(lb2);
    *(uint4*)&Bs[0][sts3] = cvt4(lb3);
    __syncthreads();

    float acc[4][8][4];
    #pragma unroll
    for (int mi = 0; mi < 4; mi++)
        #pragma unroll
        for (int ni = 0; ni < 8; ni++)
            #pragma unroll
            for (int j = 0; j < 4; j++)
                acc[mi][ni][j] = 0.0f;

    #pragma unroll 1
    for (int kc = 0; kc < nchunks; kc++) {
        const int buf = kc & 1;
        const uint32_t aS = buf ? sA1 : sA0;
        const uint32_t bS = buf ? sB1 : sB0;

        // prefetch next chunk
        if (kc + 1 < nchunks) {
            const float* Ap = A + (kc + 1) * BK;
            const float* Bp = B + (kc + 1) * BK;
            la0 = *(const float4*)(Ap + (long)r0        * K + c0);
            la1 = *(const float4*)(Ap + (long)(r0 + 32) * K + c0);
            la2 = *(const float4*)(Ap + (long)(r0 + 64) * K + c0);
            la3 = *(const float4*)(Ap + (long)(r0 + 96) * K + c0);
            lb0 = *(const float4*)(Bp + (long)r0        * K + c0);
            lb1 = *(const float4*)(Bp + (long)(r0 + 32) * K + c0);
            lb2 = *(const float4*)(Bp + (long)(r0 + 64) * K + c0);
            lb3 = *(const float4*)(Bp + (long)(r0 + 96) * K + c0);
        }

        #pragma unroll
        for (int ks = 0; ks < 2; ks++) {
            const uint32_t kByte = (uint32_t)(ks * 8) * 4u;
            uint32_t af[4][4], bf[8][2];
            #pragma unroll
            for (int mi = 0; mi < 4; mi++)
                ldsm4(af[mi][0], af[mi][1], af[mi][2], af[mi][3],
                      aS + aBase + (uint32_t)(mi * 16 * LDSS) * 4u + kByte);
            #pragma unroll
            for (int j = 0; j < 4; j++)
                ldsm4(bf[2 * j][0], bf[2 * j][1], bf[2 * j + 1][0], bf[2 * j + 1][1],
                      bS + bBase + (uint32_t)(j * 16 * LDSS) * 4u + kByte);

            #pragma unroll
            for (int mi = 0; mi < 4; mi++)
                #pragma unroll
                for (int ni = 0; ni < 8; ni++)
                    asm volatile(
                        "mma.sync.aligned.m16n8k8.row.col.f32.tf32.tf32.f32 "
                        "{%0,%1,%2,%3}, {%4,%5,%6,%7}, {%8,%9}, {%0,%1,%2,%3};"
                        : "+f"(acc[mi][ni][0]), "+f"(acc[mi][ni][1]),
                          "+f"(acc[mi][ni][2]), "+f"(acc[mi][ni][3])
                        : "r"(af[mi][0]), "r"(af[mi][1]), "r"(af[mi][2]), "r"(af[mi][3]),
                          "r"(bf[ni][0]), "r"(bf[ni][1]));
        }

        // store prefetched chunk to the other buffer
        if (kc + 1 < nchunks) {
            uint32_t* a = As[buf ^ 1];
            uint32_t* b = Bs[buf ^ 1];
            *(uint4*)&a[sts0] = cvt4(la0);
            *(uint4*)&a[sts1] = cvt4(la1);
            *(uint4*)&a[sts2] = cvt4(la2);
            *(uint4*)&a[sts3] = cvt4(la3);
            *(uint4*)&b[sts0] = cvt4(lb0);
            *(uint4*)&b[sts1] = cvt4(lb1);
            *(uint4*)&b[sts2] = cvt4(lb2);
            *(uint4*)&b[sts3] = cvt4(lb3);
        }
        __syncthreads();
    }

    // Epilogue
    #pragma unroll
    for (int mi = 0; mi < 4; mi++) {
        const long row = (long)blockIdx.y * BM + wm * 64 + mi * 16 + (lane >> 2);
        #pragma unroll
        for (int ni = 0; ni < 8; ni++) {
            const long col = (long)blockIdx.x * BN + wn * 64 + ni * 8 + (lane & 3) * 2;
            float2 v0 = make_float2(acc[mi][ni][0], acc[mi][ni][1]);
            float2 v1 = make_float2(acc[mi][ni][2], acc[mi][ni][3]);
            if (RELU) {
                v0.x = fmaxf(v0.x, 0.0f); v0.y = fmaxf(v0.y, 0.0f);
                v1.x = fmaxf(v1.x, 0.0f); v1.y = fmaxf(v1.y, 0.0f);
            }
            *(float2*)(C + row * N + col)       = v0;
            *(float2*)(C + (row + 8) * N + col) = v1;
        }
    }
}

extern "C" void kernel_launch(void* const* d_in, const int* in_sizes, int n_in,
                              void* d_out, int out_size)
{
    (void)in_sizes; (void)n_in; (void)out_size;

    const float* x   = (const float*)d_in[0];  // (8,2048,256)
    const float* mem = (const float*)d_in[1];  // (8,1024,256)
    const float* W   = (const float*)d_in[2];  // (256,256)

    float* key = (float*)d_out;                      // 16384*256
    float* val = (float*)d_out + (long)16384 * 256;  // 16384*1024

    const int smemB = SMEM_WORDS * 4;                // 40960

    static int configured = 0;
    if (!configured) {
        cudaFuncSetAttribute(tf32_mma_nt<true>,
                             cudaFuncAttributeMaxDynamicSharedMemorySize, smemB);
        cudaFuncSetAttribute(tf32_mma_nt<false>,
                             cudaFuncAttributeMaxDynamicSharedMemorySize, smemB);
        configured = 1;
    }

    // GEMM 1: key = relu(x @ W^T)  M=16384 N=256 K=256 -> grid (2,128)
    {
        dim3 grid(256 / BN, 16384 / BM, 1);
        tf32_mma_nt<true><<<grid, 128, smemB>>>(x, W, key, 256, 256, 0, 0, 0);
    }
    // GEMM 2: val[b] = key[b] @ mem[b]^T  M=2048 N=1024 K=256, batch 8 -> grid (8,16,8)
    {
        dim3 grid(1024 / BN, 2048 / BM, 8);
        tf32_mma_nt<false><<<grid, 128, smemB>>>(
            key, mem, val, 256, 1024,
            (long)2048 * 256, (long)1024 * 256, (long)2048 * 1024);
    }
}